// round 16
// baseline (speedup 1.0000x reference)
#include <cuda_runtime.h>
#include <cuda_fp16.h>

#define B_ 4
#define N_ 2048
#define C_ 1024
#define H_ 16
#define D_ 64
#define M_ (B_*N_)

// Scratch (device globals — no runtime allocation allowed)
__device__ __half xh_g[(size_t)M_*C_];
__device__ __half qwh_g[(size_t)3*C_*C_];
__device__ __half pwh_g[(size_t)C_*C_];
__device__ __half qh_g[(size_t)B_*H_*N_*D_];
__device__ __half kh_g[(size_t)B_*H_*N_*D_];
__device__ __half vh_g[(size_t)B_*H_*N_*D_];
__device__ __half atth_g[(size_t)B_*N_*C_];

__device__ __forceinline__ float ex2(float x) {
    float y; asm("ex2.approx.ftz.f32 %0, %1;" : "=f"(y) : "f"(x)); return y;
}
__device__ __forceinline__ unsigned h2(float a, float b) {
    __half2 h = __floats2half2_rn(a, b);
    return *(unsigned*)&h;
}
__device__ __forceinline__ uint4 cvt8(float4 a, float4 b) {
    uint4 u; u.x = h2(a.x, a.y); u.y = h2(a.z, a.w);
    u.z = h2(b.x, b.y); u.w = h2(b.z, b.w); return u;
}
__device__ __forceinline__ void mma16(float* c, const unsigned* a, unsigned b0, unsigned b1) {
    asm volatile("mma.sync.aligned.m16n8k16.row.col.f32.f16.f16.f32 "
        "{%0,%1,%2,%3}, {%4,%5,%6,%7}, {%8,%9}, {%0,%1,%2,%3};"
        : "+f"(c[0]), "+f"(c[1]), "+f"(c[2]), "+f"(c[3])
        : "r"(a[0]), "r"(a[1]), "r"(a[2]), "r"(a[3]), "r"(b0), "r"(b1));
}
__device__ __forceinline__ void ldsm4(unsigned* r, unsigned addr) {
    asm volatile("ldmatrix.sync.aligned.m8n8.x4.shared.b16 {%0,%1,%2,%3}, [%4];"
        : "=r"(r[0]), "=r"(r[1]), "=r"(r[2]), "=r"(r[3]) : "r"(addr));
}
__device__ __forceinline__ void ldsm4t(unsigned* r, unsigned addr) {
    asm volatile("ldmatrix.sync.aligned.m8n8.x4.trans.shared.b16 {%0,%1,%2,%3}, [%4];"
        : "=r"(r[0]), "=r"(r[1]), "=r"(r[2]), "=r"(r[3]) : "r"(addr));
}
__device__ __forceinline__ void cp16(unsigned dst, const void* src) {
    asm volatile("cp.async.cg.shared.global [%0], [%1], 16;" :: "r"(dst), "l"(src));
}
__device__ __forceinline__ void cp_commit() {
    asm volatile("cp.async.commit_group;" ::: "memory");
}

// Rows are 64 halves = 128 bytes = 8 chunks of 16B; XOR swizzle on chunks.
__device__ __forceinline__ unsigned hswz(int row, int chunk) {   // byte offset
    return (unsigned)(row * 128 + (((chunk ^ (row & 7)) << 4)));
}

// ---------------------------------------------------------------------------
// fp32 -> fp16 pre-conversion (x, qkv_w, proj_w) — single fused launch
// ---------------------------------------------------------------------------
#define NX (M_*C_)
#define NQW (3*C_*C_)
#define NPW (C_*C_)

__global__ __launch_bounds__(256) void cvt_kernel(const float* __restrict__ x,
                                                  const float* __restrict__ qw,
                                                  const float* __restrict__ pw)
{
    int i = (blockIdx.x * 256 + threadIdx.x) * 8;
    const float* src;
    __half* dst;
    if (i < NX)            { src = x + i;              dst = xh_g + i; }
    else if (i < NX + NQW) { src = qw + (i - NX);      dst = qwh_g + (i - NX); }
    else                   { src = pw + (i - NX - NQW); dst = pwh_g + (i - NX - NQW); }
    float4 a = *(const float4*)src;
    float4 b = *(const float4*)(src + 4);
    *(uint4*)dst = cvt8(a, b);
}

// ---------------------------------------------------------------------------
// GEMM core: C_tile[128x128] = A[128xK] * W[128xK]^T, K=1024, fp16 in gmem.
// 128 threads, 4 warps (2x2), warp tile 64x64. Stage = 64 K-halves,
// cp.async 3-stage ring, 1 barrier per stage. LDSM/MMA interleaved k-step.
// ---------------------------------------------------------------------------
#define STGB 32768   // bytes per stage (A 16KB + B 16KB)
#define NSTG 16      // 1024 / 64
#define GEMM_SMEM (3*STGB)

__device__ __forceinline__ void g_issue(unsigned sb, unsigned ring,
                                        const __half* Ap, const __half* Wp,
                                        int kc, int lrow, int lch)
{
    #pragma unroll
    for (int t = 0; t < 8; t++)
        cp16(sb + ring + hswz(lrow + 16 * t, lch), Ap + (size_t)(16 * t) * C_ + kc);
    #pragma unroll
    for (int t = 0; t < 8; t++)
        cp16(sb + ring + 16384u + hswz(lrow + 16 * t, lch), Wp + (size_t)(16 * t) * C_ + kc);
}

#define MMAJ(j)                                                             \
        _Pragma("unroll")                                                   \
        for (int i = 0; i < 4; i++) {                                       \
            mma16(acc[i][2 * (j)],     af[i], bf[j][0], bf[j][2]);          \
            mma16(acc[i][2 * (j) + 1], af[i], bf[j][1], bf[j][3]);          \
        }

#define KSTEPH(ks)                                                          \
    {                                                                       \
        unsigned af[4][4], bf[4][4];                                        \
        _Pragma("unroll")                                                   \
        for (int i = 0; i < 4; i++)                                         \
            ldsm4(af[i], abase + hswz(wm * 64 + i * 16 + mrow_l, 2 * (ks) + chk_l)); \
        ldsm4(bf[0], bbase + hswz(wn * 64 + 0 * 16 + mrow_l, 2 * (ks) + chk_l)); \
        ldsm4(bf[1], bbase + hswz(wn * 64 + 1 * 16 + mrow_l, 2 * (ks) + chk_l)); \
        MMAJ(0)                                                             \
        ldsm4(bf[2], bbase + hswz(wn * 64 + 2 * 16 + mrow_l, 2 * (ks) + chk_l)); \
        MMAJ(1)                                                             \
        ldsm4(bf[3], bbase + hswz(wn * 64 + 3 * 16 + mrow_l, 2 * (ks) + chk_l)); \
        MMAJ(2)                                                             \
        MMAJ(3)                                                             \
    }

__device__ __forceinline__ void gemm_h(const __half* __restrict__ A,
                                       const __half* __restrict__ W,
                                       int bm, int bn,
                                       float acc[4][8][4], char* smb)
{
    int tid = threadIdx.x, wid = tid >> 5, lane = tid & 31;
    int wm = wid >> 1, wn = wid & 1;
    unsigned sb = (unsigned)__cvta_generic_to_shared(smb);

    int lrow = tid >> 3;            // 0..15, rows +16t
    int lch = tid & 7;              // 16B chunk
    int mrow_l = (lane & 7) + (((lane >> 3) & 1) << 3);
    int chk_l = lane >> 4;

    const __half* Ap = A + (size_t)(bm + lrow) * C_ + lch * 8;
    const __half* Wp = W + (size_t)(bn + lrow) * C_ + lch * 8;

    g_issue(sb, 0, Ap, Wp, 0, lrow, lch);  cp_commit();
    g_issue(sb, STGB, Ap, Wp, 64, lrow, lch);  cp_commit();

    for (int s = 0; s < NSTG; s++) {
        if (s < NSTG - 1) asm volatile("cp.async.wait_group 1;" ::: "memory");
        else              asm volatile("cp.async.wait_group 0;" ::: "memory");
        __syncthreads();
        if (s + 2 < NSTG) {
            g_issue(sb, (unsigned)((s + 2) % 3) * STGB, Ap, Wp, (s + 2) * 64, lrow, lch);
            cp_commit();
        }
        unsigned abase = sb + (unsigned)(s % 3) * STGB;
        unsigned bbase = abase + 16384u;
        KSTEPH(0)
        KSTEPH(1)
        KSTEPH(2)
        KSTEPH(3)
    }
    __syncthreads();
}

// ---------------------------------------------------------------------------
// GEMM 1: qkv = x @ qkv_w^T -> fp16 q(scaled)/k/v [B,H,N,D]
// ---------------------------------------------------------------------------
#define SC2F 0.18033688f   // 0.125 * log2(e)

__global__ __launch_bounds__(128, 2) void qkv_gemm()
{
    extern __shared__ char smc[];
    int bm = blockIdx.y * 128, bn = blockIdx.x * 128;
    float acc[4][8][4];
    #pragma unroll
    for (int i = 0; i < 4; i++)
        #pragma unroll
        for (int j = 0; j < 8; j++)
            #pragma unroll
            for (int q = 0; q < 4; q++) acc[i][j][q] = 0.f;

    gemm_h(xh_g, qwh_g, bm, bn, acc, smc);

    int tid = threadIdx.x, wid = tid >> 5, lane = tid & 31;
    int wm = wid >> 1, wn = wid & 1;
    int g = lane >> 2, tg = lane & 3;

    #pragma unroll
    for (int i = 0; i < 4; i++) {
        #pragma unroll
        for (int j = 0; j < 8; j++) {
            int col = bn + wn * 64 + j * 8 + 2 * tg;
            int three = col >> 10, rem = col & 1023;
            int h = rem >> 6, d = rem & 63;
            __half* dst = (three == 0) ? qh_g : (three == 1 ? kh_g : vh_g);
            float sc = (three == 0) ? SC2F : 1.0f;
            #pragma unroll
            for (int half = 0; half < 2; half++) {
                int row = bm + wm * 64 + i * 16 + g + half * 8;
                int b = row >> 11, n = row & (N_ - 1);
                *(unsigned*)(dst + (((size_t)b * H_ + h) * N_ + n) * D_ + d) =
                    h2(acc[i][j][half * 2] * sc, acc[i][j][half * 2 + 1] * sc);
            }
        }
    }
}

// ---------------------------------------------------------------------------
// GEMM 2: out = atth @ proj_w^T + proj_b  (fp32 out)
// ---------------------------------------------------------------------------
__global__ __launch_bounds__(128, 2) void proj_gemm(const float* __restrict__ bias,
                                                    float* __restrict__ out)
{
    extern __shared__ char smc[];
    int bm = blockIdx.y * 128, bn = blockIdx.x * 128;
    float acc[4][8][4];
    #pragma unroll
    for (int i = 0; i < 4; i++)
        #pragma unroll
        for (int j = 0; j < 8; j++)
            #pragma unroll
            for (int q = 0; q < 4; q++) acc[i][j][q] = 0.f;

    gemm_h(atth_g, pwh_g, bm, bn, acc, smc);

    int tid = threadIdx.x, wid = tid >> 5, lane = tid & 31;
    int wm = wid >> 1, wn = wid & 1;
    int g = lane >> 2, tg = lane & 3;

    #pragma unroll
    for (int i = 0; i < 4; i++) {
        #pragma unroll
        for (int j = 0; j < 8; j++) {
            int col = bn + wn * 64 + j * 8 + 2 * tg;
            float b0 = bias[col], b1 = bias[col + 1];
            #pragma unroll
            for (int half = 0; half < 2; half++) {
                int row = bm + wm * 64 + i * 16 + g + half * 8;
                float2 v = {acc[i][j][half * 2] + b0, acc[i][j][half * 2 + 1] + b1};
                *(float2*)(out + (size_t)row * C_ + col) = v;
            }
        }
    }
}

// ---------------------------------------------------------------------------
// Causal flash attention, fp16. Block = (qtile 128, head, batch), 4 warps x
// 32 q-rows. P in registers; V via ldmatrix.trans.
// 3-slot KV ring, prefetch 2 tiles ahead, ONE barrier per k-tile.
// smem: Q [0,16K) | slot0 | slot1 | slot2  = 64KB.
// ---------------------------------------------------------------------------
#define QSB 0
#define RK(r) (16384u + (unsigned)(r) * 16384u)
#define RV(r) (RK(r) + 8192u)
#define ATT_SMEM 65536

__device__ __forceinline__ void kv_issue(unsigned sb, int slot, int kt,
                                         const __half* Kg, const __half* Vg,
                                         int krow, int kch)
{
    #pragma unroll
    for (int t = 0; t < 2; t++) {
        int row = krow + 32 * t;
        #pragma unroll
        for (int cc = 0; cc < 2; cc++) {
            int ch = kch + 4 * cc;
            const __half* ks = Kg + (size_t)(kt * 64 + row) * D_ + ch * 8;
            const __half* vs = Vg + (size_t)(kt * 64 + row) * D_ + ch * 8;
            cp16(sb + RK(slot) + hswz(row, ch), ks);
            cp16(sb + RV(slot) + hswz(row, ch), vs);
        }
    }
}

__global__ __launch_bounds__(128, 2) void attn_kernel()
{
    extern __shared__ char smc[];
    unsigned sb = (unsigned)__cvta_generic_to_shared(smc);

    int qt = (int)(gridDim.x - 1 - blockIdx.x);   // heavy tiles first
    int hh = blockIdx.y, b = blockIdx.z;
    int tid = threadIdx.x, w = tid >> 5, lane = tid & 31;
    int g = lane >> 2, tg = lane & 3;
    int wr = w * 32;

    int mrow_l = (lane & 7) + (((lane >> 3) & 1) << 3);
    int chk_l = lane >> 4;

    const __half* Qg = qh_g + ((size_t)b * H_ + hh) * N_ * D_;
    const __half* Kg = kh_g + ((size_t)b * H_ + hh) * N_ * D_;
    const __half* Vg = vh_g + ((size_t)b * H_ + hh) * N_ * D_;

    int lrow = tid >> 3, lch = tid & 7;            // Q loader
    int krow = tid >> 2, kch = tid & 3;            // K/V loader

    int nkt = 2 * qt + 2;

    // prologue: Q + KV0 (group 0), KV1 (group 1)
    #pragma unroll
    for (int t = 0; t < 8; t++)
        cp16(sb + QSB + hswz(lrow + 16 * t, lch),
             Qg + (size_t)(qt * 128 + lrow + 16 * t) * D_ + lch * 8);
    kv_issue(sb, 0, 0, Kg, Vg, krow, kch);
    cp_commit();
    kv_issue(sb, 1, 1, Kg, Vg, krow, kch);   // nkt >= 2 always
    cp_commit();

    float o[2][8][4];
    #pragma unroll
    for (int i = 0; i < 2; i++)
        #pragma unroll
        for (int nt = 0; nt < 8; nt++)
            #pragma unroll
            for (int q = 0; q < 4; q++) o[i][nt][q] = 0.f;
    float mrow[2][2], lrow_[2][2];
    #pragma unroll
    for (int i = 0; i < 2; i++) { mrow[i][0] = mrow[i][1] = -1e30f; lrow_[i][0] = lrow_[i][1] = 0.f; }

    for (int kt = 0; kt < nkt; kt++) {
        // wait until KV(kt) has landed
        if (kt + 1 < nkt) asm volatile("cp.async.wait_group 1;" ::: "memory");
        else              asm volatile("cp.async.wait_group 0;" ::: "memory");
        __syncthreads();   // KV(kt) visible; slot (kt+2)%3 reads (iter kt-1) done

        if (kt + 2 < nkt) {
            kv_issue(sb, (kt + 2) % 3, kt + 2, Kg, Vg, krow, kch);
            cp_commit();
        }

        bool active = !(kt * 64 > qt * 128 + wr + 31);
        unsigned kbase = sb + RK(kt % 3);
        unsigned vbase = sb + RV(kt % 3);

        if (active) {
            // S = Q K^T  (k16 steps)
            float s[2][8][4];
            #pragma unroll
            for (int i = 0; i < 2; i++)
                #pragma unroll
                for (int nt = 0; nt < 8; nt++)
                    #pragma unroll
                    for (int q = 0; q < 4; q++) s[i][nt][q] = 0.f;

            #pragma unroll
            for (int ks = 0; ks < 4; ks++) {
                unsigned kf[4][4];
                #pragma unroll
                for (int jp = 0; jp < 4; jp++)
                    ldsm4(kf[jp], kbase + hswz(jp * 16 + mrow_l, 2 * ks + chk_l));
                #pragma unroll
                for (int i = 0; i < 2; i++) {
                    unsigned qf[4];
                    ldsm4(qf, sb + QSB + hswz(wr + i * 16 + mrow_l, 2 * ks + chk_l));
                    #pragma unroll
                    for (int jp = 0; jp < 4; jp++) {
                        mma16(s[i][2 * jp],     qf, kf[jp][0], kf[jp][2]);
                        mma16(s[i][2 * jp + 1], qf, kf[jp][1], kf[jp][3]);
                    }
                }
            }

            // causal mask (tiles straddling the diagonal)
            if (kt * 64 + 63 > qt * 128 + wr) {
                #pragma unroll
                for (int i = 0; i < 2; i++) {
                    int row0 = qt * 128 + wr + i * 16 + g;
                    #pragma unroll
                    for (int nt = 0; nt < 8; nt++) {
                        int c0 = kt * 64 + nt * 8 + 2 * tg;
                        if (c0 > row0)         s[i][nt][0] = -1e30f;
                        if (c0 + 1 > row0)     s[i][nt][1] = -1e30f;
                        if (c0 > row0 + 8)     s[i][nt][2] = -1e30f;
                        if (c0 + 1 > row0 + 8) s[i][nt][3] = -1e30f;
                    }
                }
            }

            // online softmax (exp2 domain) — exp values kept in s[][][]
            #pragma unroll
            for (int i = 0; i < 2; i++) {
                float mx0 = -1e30f, mx1 = -1e30f;
                #pragma unroll
                for (int nt = 0; nt < 8; nt++) {
                    mx0 = fmaxf(mx0, fmaxf(s[i][nt][0], s[i][nt][1]));
                    mx1 = fmaxf(mx1, fmaxf(s[i][nt][2], s[i][nt][3]));
                }
                mx0 = fmaxf(mx0, __shfl_xor_sync(0xffffffffu, mx0, 1));
                mx0 = fmaxf(mx0, __shfl_xor_sync(0xffffffffu, mx0, 2));
                mx1 = fmaxf(mx1, __shfl_xor_sync(0xffffffffu, mx1, 1));
                mx1 = fmaxf(mx1, __shfl_xor_sync(0xffffffffu, mx1, 2));

                float nm0 = fmaxf(mrow[i][0], mx0), nm1 = fmaxf(mrow[i][1], mx1);
                float a0 = ex2(mrow[i][0] - nm0), a1 = ex2(mrow[i][1] - nm1);
                mrow[i][0] = nm0; mrow[i][1] = nm1;

                float ls0 = 0.f, ls1 = 0.f;
                #pragma unroll
                for (int nt = 0; nt < 8; nt++) {
                    s[i][nt][0] = ex2(s[i][nt][0] - nm0);
                    s[i][nt][1] = ex2(s[i][nt][1] - nm0);
                    s[i][nt][2] = ex2(s[i][nt][2] - nm1);
                    s[i][nt][3] = ex2(s[i][nt][3] - nm1);
                    ls0 += s[i][nt][0] + s[i][nt][1];
                    ls1 += s[i][nt][2] + s[i][nt][3];
                }
                ls0 += __shfl_xor_sync(0xffffffffu, ls0, 1);
                ls0 += __shfl_xor_sync(0xffffffffu, ls0, 2);
                ls1 += __shfl_xor_sync(0xffffffffu, ls1, 1);
                ls1 += __shfl_xor_sync(0xffffffffu, ls1, 2);
                lrow_[i][0] = lrow_[i][0] * a0 + ls0;
                lrow_[i][1] = lrow_[i][1] * a1 + ls1;

                #pragma unroll
                for (int nt = 0; nt < 8; nt++) {
                    o[i][nt][0] *= a0; o[i][nt][1] *= a0;
                    o[i][nt][2] *= a1; o[i][nt][3] *= a1;
                }
            }

            // O += P V  (P packed from registers; V via ldmatrix.trans)
            #pragma unroll
            for (int ks = 0; ks < 4; ks++) {
                unsigned vf[4][4];
                #pragma unroll
                for (int nt2 = 0; nt2 < 4; nt2++)
                    ldsm4t(vf[nt2], vbase + hswz(16 * ks + mrow_l, 2 * nt2 + chk_l));
                #pragma unroll
                for (int i = 0; i < 2; i++) {
                    unsigned pf[4];
                    pf[0] = h2(s[i][2 * ks][0],     s[i][2 * ks][1]);
                    pf[1] = h2(s[i][2 * ks][2],     s[i][2 * ks][3]);
                    pf[2] = h2(s[i][2 * ks + 1][0], s[i][2 * ks + 1][1]);
                    pf[3] = h2(s[i][2 * ks + 1][2], s[i][2 * ks + 1][3]);
                    #pragma unroll
                    for (int nt2 = 0; nt2 < 4; nt2++) {
                        mma16(o[i][2 * nt2],     pf, vf[nt2][0], vf[nt2][1]);
                        mma16(o[i][2 * nt2 + 1], pf, vf[nt2][2], vf[nt2][3]);
                    }
                }
            }
        }
    }

    // epilogue: normalize + write fp16 [B,N,C]
    __half* Og = atth_g + (size_t)b * N_ * C_ + (size_t)hh * 64;
    #pragma unroll
    for (int i = 0; i < 2; i++) {
        #pragma unroll
        for (int half = 0; half < 2; half++) {
            float inv = 1.f / lrow_[i][half];
            int row = qt * 128 + wr + i * 16 + g + half * 8;
            #pragma unroll
            for (int nt = 0; nt < 8; nt++) {
                int d = nt * 8 + 2 * tg;
                *(unsigned*)(Og + (size_t)row * C_ + d) =
                    h2(o[i][nt][half * 2] * inv, o[i][nt][half * 2 + 1] * inv);
            }
        }
    }
}

// ---------------------------------------------------------------------------
extern "C" void kernel_launch(void* const* d_in, const int* in_sizes, int n_in,
                              void* d_out, int out_size)
{
    const float* x      = (const float*)d_in[0];
    const float* qkv_w  = (const float*)d_in[1];
    const float* proj_w = (const float*)d_in[2];
    const float* proj_b = (const float*)d_in[3];
    float* out = (float*)d_out;

    cudaFuncSetAttribute(qkv_gemm, cudaFuncAttributeMaxDynamicSharedMemorySize, GEMM_SMEM);
    cudaFuncSetAttribute(proj_gemm, cudaFuncAttributeMaxDynamicSharedMemorySize, GEMM_SMEM);
    cudaFuncSetAttribute(attn_kernel, cudaFuncAttributeMaxDynamicSharedMemorySize, ATT_SMEM);

    cvt_kernel<<<(NX + NQW + NPW) / (256 * 8), 256>>>(x, qkv_w, proj_w);
    qkv_gemm<<<dim3(24, 64), 128, GEMM_SMEM>>>();
    attn_kernel<<<dim3(N_ / 128, H_, B_), 128, ATT_SMEM>>>();
    proj_gemm<<<dim3(8, 64), 128, GEMM_SMEM>>>(proj_b, out);
}